// round 9
// baseline (speedup 1.0000x reference)
#include <cuda_runtime.h>
#include <cstdint>

// out = noise * gamma * sqrt(spread_bits(trunc(x * 2^14))) / 2^14
// spread_bits: bit k of w -> bit 2k, i.e. sum_k 4^k * bit_k = sum_k (2^k*bit_k)^2

__device__ __forceinline__ unsigned spread16(unsigned v) {
    v = (v | (v << 8)) & 0x00FF00FFu;
    v = (v | (v << 4)) & 0x0F0F0F0Fu;
    v = (v | (v << 2)) & 0x33333333u;
    v = (v | (v << 1)) & 0x55555555u;
    return v;
}

__device__ __forceinline__ float sigma_elem(float x) {
    int w = (int)(x * 16384.0f);
    unsigned acc = spread16((unsigned)w);
    return sqrtf((float)acc) * (0.05f / 16384.0f);
}

// 256-bit vector load/store (sm_100+), streaming policy (single-touch data).
__device__ __forceinline__ void ldg256_cs(const float* p, float* r) {
    asm volatile(
        "ld.global.cs.v8.f32 {%0,%1,%2,%3,%4,%5,%6,%7}, [%8];"
        : "=f"(r[0]), "=f"(r[1]), "=f"(r[2]), "=f"(r[3]),
          "=f"(r[4]), "=f"(r[5]), "=f"(r[6]), "=f"(r[7])
        : "l"(p));
}

__device__ __forceinline__ void stg256_cs(float* p, const float* r) {
    asm volatile(
        "st.global.cs.v8.f32 [%0], {%1,%2,%3,%4,%5,%6,%7,%8};"
        :: "l"(p),
           "f"(r[0]), "f"(r[1]), "f"(r[2]), "f"(r[3]),
           "f"(r[4]), "f"(r[5]), "f"(r[6]), "f"(r[7])
        : "memory");
}

// Persistent grid: 8 CTAs per SM, each thread walks the array with a
// grid-wide stride of v8 chunks. Software pipeline: next iteration's loads
// are issued before the current iteration's compute+store, so the DRAM
// latency (577 cyc) is exposed only once per CTA instead of once per tile.
__global__ void __launch_bounds__(256) weight_noise_kernel(
        const float* __restrict__ x,
        const float* __restrict__ noise,
        float* __restrict__ out,
        long long n8,      // number of full v8 chunks
        long long n) {     // total elements
    long long stride = (long long)gridDim.x * blockDim.x;       // threads total
    long long t = (long long)blockIdx.x * blockDim.x + threadIdx.x;

    float xv[8], nv[8], xn[8], nn[8], ov[8];

    long long i = t;
    if (i < n8) {
        ldg256_cs(x + i * 8, xv);
        ldg256_cs(noise + i * 8, nv);
    }
    while (i < n8) {
        long long inext = i + stride;
        if (inext < n8) {
            ldg256_cs(x + inext * 8, xn);
            ldg256_cs(noise + inext * 8, nn);
        }
        #pragma unroll
        for (int k = 0; k < 8; k++)
            ov[k] = nv[k] * sigma_elem(xv[k]);
        stg256_cs(out + i * 8, ov);
        #pragma unroll
        for (int k = 0; k < 8; k++) { xv[k] = xn[k]; nv[k] = nn[k]; }
        i = inext;
    }

    // Scalar tail (n not divisible by 8) — thread 0 of block 0 handles it.
    if (blockIdx.x == 0 && threadIdx.x == 0) {
        for (long long j = n8 * 8; j < n; j++)
            out[j] = noise[j] * sigma_elem(x[j]);
    }
}

extern "C" void kernel_launch(void* const* d_in, const int* in_sizes, int n_in,
                              void* d_out, int out_size) {
    const float* x = (const float*)d_in[0];
    const float* noise = (const float*)d_in[1];
    float* out = (float*)d_out;
    long long n = in_sizes[0];            // 33554432
    long long n8 = n / 8;                 // 4194304 v8 chunks
    int threads = 256;
    int blocks = 148 * 8;                 // persistent: 8 CTAs/SM
    long long nthreads = (n8 + 0);        // ensure we never launch more than needed
    long long need_blocks = (n8 + threads - 1) / threads;
    if (need_blocks < blocks) blocks = (int)need_blocks;
    weight_noise_kernel<<<blocks, threads>>>(x, noise, out, n8, n);
}

// round 10
// speedup vs baseline: 1.0283x; 1.0283x over previous
#include <cuda_runtime.h>
#include <cstdint>

// out = noise * gamma * sqrt(spread_bits(trunc(x * 2^14))) / 2^14
// spread_bits: bit k of w -> bit 2k, i.e. sum_k 4^k * bit_k = sum_k (2^k*bit_k)^2
// (closed form of the reference's bit-decomposition while-loop)

__device__ __forceinline__ unsigned spread16(unsigned v) {
    v = (v | (v << 8)) & 0x00FF00FFu;
    v = (v | (v << 4)) & 0x0F0F0F0Fu;
    v = (v | (v << 2)) & 0x33333333u;
    v = (v | (v << 1)) & 0x55555555u;
    return v;
}

__device__ __forceinline__ float sigma_elem(float x) {
    int w = (int)(x * 16384.0f);          // trunc toward zero, matches int cast
    unsigned acc = spread16((unsigned)w);
    return sqrtf((float)acc) * (0.05f / 16384.0f);   // gamma / 2^wf_bits
}

// 256-bit vector load/store (sm_100+): LDG.E.256 / STG.E.256, streaming
// policy — every byte is touched exactly once, evict-first keeps L2 clean.
__device__ __forceinline__ void ldg256_cs(const float* p, float* r) {
    asm volatile(
        "ld.global.cs.v8.f32 {%0,%1,%2,%3,%4,%5,%6,%7}, [%8];"
        : "=f"(r[0]), "=f"(r[1]), "=f"(r[2]), "=f"(r[3]),
          "=f"(r[4]), "=f"(r[5]), "=f"(r[6]), "=f"(r[7])
        : "l"(p));
}

__device__ __forceinline__ void stg256_cs(float* p, const float* r) {
    asm volatile(
        "st.global.cs.v8.f32 [%0], {%1,%2,%3,%4,%5,%6,%7,%8};"
        :: "l"(p),
           "f"(r[0]), "f"(r[1]), "f"(r[2]), "f"(r[3]),
           "f"(r[4]), "f"(r[5]), "f"(r[6]), "f"(r[7])
        : "memory");
}

// Final form (best measured: 52.32us, 7.70 TB/s effective = 96% of HBM spec).
// 256 threads/block, one v8 (32B) per thread per array: consecutive threads
// touch consecutive 32B chunks -> 1KB/warp per load instruction, fully
// coalesced. regs=28 -> 8 CTAs/SM, occ ~81%. HBM-bound; compute pipes <40%.
__global__ void __launch_bounds__(256) weight_noise_kernel(
        const float* __restrict__ x,
        const float* __restrict__ noise,
        float* __restrict__ out,
        int n) {
    long long t = (long long)blockIdx.x * blockDim.x + threadIdx.x;
    long long i = t * 8;
    if (i + 8 <= n) {
        float xv[8], nv[8], ov[8];
        ldg256_cs(x + i, xv);
        ldg256_cs(noise + i, nv);
        #pragma unroll
        for (int k = 0; k < 8; k++)
            ov[k] = nv[k] * sigma_elem(xv[k]);
        stg256_cs(out + i, ov);
    } else {
        for (long long j = i; j < n; j++)
            out[j] = noise[j] * sigma_elem(x[j]);
    }
}

extern "C" void kernel_launch(void* const* d_in, const int* in_sizes, int n_in,
                              void* d_out, int out_size) {
    const float* x = (const float*)d_in[0];
    const float* noise = (const float*)d_in[1];
    float* out = (float*)d_out;
    int n = in_sizes[0];                      // 33554432
    int threads = 256;
    long long nthreads = (n + 7) / 8;         // 8 floats per thread
    int blocks = (int)((nthreads + threads - 1) / threads);  // 16384 exact
    weight_noise_kernel<<<blocks, threads>>>(x, noise, out, n);
}

// round 11
// speedup vs baseline: 1.0325x; 1.0041x over previous
#include <cuda_runtime.h>
#include <cstdint>

// out = noise * gamma * sqrt(spread_bits(trunc(x * 2^14))) / 2^14
// spread_bits: bit k of w -> bit 2k, i.e. sum_k 4^k * bit_k = sum_k (2^k*bit_k)^2
// (closed form of the reference's bit-decomposition while-loop)

__device__ __forceinline__ unsigned spread16(unsigned v) {
    v = (v | (v << 8)) & 0x00FF00FFu;
    v = (v | (v << 4)) & 0x0F0F0F0Fu;
    v = (v | (v << 2)) & 0x33333333u;
    v = (v | (v << 1)) & 0x55555555u;
    return v;
}

__device__ __forceinline__ float sigma_elem(float x) {
    int w = (int)(x * 16384.0f);          // trunc toward zero, matches int cast
    unsigned acc = spread16((unsigned)w);
    return sqrtf((float)acc) * (0.05f / 16384.0f);   // gamma / 2^wf_bits
}

// 256-bit loads via the non-coherent read-only path (LDG.E.NC.256);
// 256-bit stores with streaming (evict-first) policy — single-touch data.
__device__ __forceinline__ void ldg256_nc(const float* p, float* r) {
    asm volatile(
        "ld.global.nc.v8.f32 {%0,%1,%2,%3,%4,%5,%6,%7}, [%8];"
        : "=f"(r[0]), "=f"(r[1]), "=f"(r[2]), "=f"(r[3]),
          "=f"(r[4]), "=f"(r[5]), "=f"(r[6]), "=f"(r[7])
        : "l"(p));
}

__device__ __forceinline__ void stg256_cs(float* p, const float* r) {
    asm volatile(
        "st.global.cs.v8.f32 [%0], {%1,%2,%3,%4,%5,%6,%7,%8};"
        :: "l"(p),
           "f"(r[0]), "f"(r[1]), "f"(r[2]), "f"(r[3]),
           "f"(r[4]), "f"(r[5]), "f"(r[6]), "f"(r[7])
        : "memory");
}

// Best measured family (52.3-53.5us band, ~7.7 TB/s effective = 96% of HBM
// spec). 256 threads/block, one v8 (32B) per thread per array: consecutive
// threads -> consecutive 32B chunks -> 1KB/warp per load instruction, fully
// coalesced. regs~28 -> 8 CTAs/SM.
__global__ void __launch_bounds__(256) weight_noise_kernel(
        const float* __restrict__ x,
        const float* __restrict__ noise,
        float* __restrict__ out,
        int n) {
    long long t = (long long)blockIdx.x * blockDim.x + threadIdx.x;
    long long i = t * 8;
    if (i + 8 <= n) {
        float xv[8], nv[8], ov[8];
        ldg256_nc(x + i, xv);
        ldg256_nc(noise + i, nv);
        #pragma unroll
        for (int k = 0; k < 8; k++)
            ov[k] = nv[k] * sigma_elem(xv[k]);
        stg256_cs(out + i, ov);
    } else {
        for (long long j = i; j < n; j++)
            out[j] = noise[j] * sigma_elem(x[j]);
    }
}

extern "C" void kernel_launch(void* const* d_in, const int* in_sizes, int n_in,
                              void* d_out, int out_size) {
    const float* x = (const float*)d_in[0];
    const float* noise = (const float*)d_in[1];
    float* out = (float*)d_out;
    int n = in_sizes[0];                      // 33554432
    int threads = 256;
    long long nthreads = (n + 7) / 8;         // 8 floats per thread
    int blocks = (int)((nthreads + threads - 1) / threads);  // 16384 exact
    weight_noise_kernel<<<blocks, threads>>>(x, noise, out, n);
}